// round 10
// baseline (speedup 1.0000x reference)
#include <cuda_runtime.h>
#include <math.h>

#define LEAKY_SLOPE 0.01f
#define EPS_C 0.1f
#define GAMMA_C 0.1f

#define NN 50000
#define EE 600000

// ---------------- scratch (node/edge data only; NO weight-copy arrays) ----------------
__device__ __align__(16) float g_h   [NN * 128];
__device__ __align__(16) float g_h2  [NN * 64];
__device__ __align__(16) float g_buf [NN * 256];   // fused [msg | anti] rows
__device__ int   g_deg   [NN];
__device__ float g_dinv  [NN];
__device__ int   g_src   [EE];
__device__ int   g_dst   [EE];
__device__ int   g_rowptr[NN + 1];
__device__ int   g_cursor[NN];
__device__ int   g_colidx[EE];
__device__ int   g_is64;

__device__ __forceinline__ float lky(float x) { return x > 0.f ? x : LEAKY_SLOPE * x; }
__device__ __forceinline__ int clampN(int v) { return v < 0 ? 0 : (v >= NN ? NN - 1 : v); }

// ---------------- probe (launch #1) ----------------
__global__ void probe_kernel(const unsigned int* __restrict__ w) {
    __shared__ int fl;
    if (threadIdx.x == 0) fl = 0;
    __syncthreads();
    for (int i = 1 + 2 * (int)threadIdx.x; i < 16384; i += 2 * (int)blockDim.x)
        if (w[i] != 0u) fl = 1;
    __syncthreads();
    if (threadIdx.x == 0) g_is64 = (fl == 0) ? 1 : 0;
}

// ---------------- convert + zero_deg fused (launch #2) ----------------
__global__ void convert_zero(const void* __restrict__ raw) {
    int i = blockIdx.x * blockDim.x + threadIdx.x;
    if (i < NN) g_deg[i] = 0;
    if (i >= EE) return;
    int s, d;
    if (g_is64) {
        const long long* p = (const long long*)raw;
        s = (int)p[i];
        d = (int)p[EE + i];
    } else {
        const int* p = (const int*)raw;
        s = p[i];
        d = p[EE + i];
    }
    g_src[i] = clampN(s);
    g_dst[i] = clampN(d);
}

// ---------------- hist (launch #3) ----------------
__global__ void hist_kernel() {
    int i = blockIdx.x * blockDim.x + threadIdx.x;
    if (i < EE) atomicAdd(&g_deg[g_dst[i]], 1);
}

// ---------------- degree norm ----------------
__global__ void dinv_kernel() {
    int i = blockIdx.x * blockDim.x + threadIdx.x;
    if (i < NN) g_dinv[i] = rsqrtf((float)(g_deg[i] + 1));  // +1 self loop
}

// ---------------- CSR build (by dst), verbatim R9 ----------------
__global__ void scan_kernel() {
    __shared__ int sh[1024];
    __shared__ int carry;
    int t = threadIdx.x;
    if (t == 0) carry = 0;
    __syncthreads();
    for (int base = 0; base < NN; base += 1024) {
        int v = (base + t < NN) ? g_deg[base + t] : 0;
        sh[t] = v;
        __syncthreads();
        for (int off = 1; off < 1024; off <<= 1) {
            int add = (t >= off) ? sh[t - off] : 0;
            __syncthreads();
            sh[t] += add;
            __syncthreads();
        }
        int incl = sh[t];
        int excl = carry + incl - v;
        if (base + t < NN) g_rowptr[base + t] = excl;
        __syncthreads();
        if (t == 1023) carry += incl;
        __syncthreads();
    }
    if (t == 0) g_rowptr[NN] = carry;
}
__global__ void cursor_copy() {
    int i = blockIdx.x * blockDim.x + threadIdx.x;
    if (i < NN) g_cursor[i] = g_rowptr[i];
}
__global__ void fill_kernel() {
    int i = blockIdx.x * blockDim.x + threadIdx.x;
    if (i >= EE) return;
    int d = g_dst[i];
    int p = atomicAdd(&g_cursor[d], 1);
    if (p < EE) g_colidx[p] = g_src[i];
}

// ---------------- tiled GEMM, B built on the fly from RAW weights (verbatim R9) --------------
template<int K, int J, int BMODE, int PREL, int POSTL>
__global__ void __launch_bounds__(256)
gemm_kernel(const float* __restrict__ A, const float* __restrict__ W1,
            const float* __restrict__ W2, const float* __restrict__ bias,
            float* __restrict__ C) {
    __shared__ float sA[16][128 + 4];
    __shared__ float sB[16][64];
    int tid = threadIdx.x;
    int tx = tid & 15;
    int ty = tid >> 4;
    int row0 = blockIdx.x * 128;
    int col0 = blockIdx.y * 64;
    constexpr int HALF = J / 2;

    float acc[8][4];
#pragma unroll
    for (int r = 0; r < 8; r++)
#pragma unroll
        for (int c = 0; c < 4; c++) acc[r][c] = 0.f;

    for (int kt = 0; kt < K; kt += 16) {
#pragma unroll
        for (int li = 0; li < 2; li++) {
            int idx = tid + li * 256;
            int r = idx >> 2;
            int k4 = (idx & 3) * 4;
            float4 v = make_float4(0.f, 0.f, 0.f, 0.f);
            int gr = row0 + r;
            if (gr < NN) v = *(const float4*)(A + (size_t)gr * K + kt + k4);
            if (PREL) { v.x = lky(v.x); v.y = lky(v.y); v.z = lky(v.z); v.w = lky(v.w); }
            sA[k4 + 0][r] = v.x;
            sA[k4 + 1][r] = v.y;
            sA[k4 + 2][r] = v.z;
            sA[k4 + 3][r] = v.w;
        }
        {
            int k = tid >> 4;
            int j4 = (tid & 15) * 4;
            int kk = kt + k;
#pragma unroll
            for (int i = 0; i < 4; i++) {
                int j = col0 + j4 + i;
                float v;
                if (BMODE == 0) {
                    v = W1[(size_t)j * K + kk];
                } else {
                    if (j < HALF) {
                        v = W1[(size_t)kk * HALF + j];
                    } else {
                        int jj = j - HALF;
                        v = W2[(size_t)jj * HALF + kk] - W2[(size_t)kk * HALF + jj]
                            - ((kk == jj) ? GAMMA_C : 0.f);
                    }
                }
                sB[k][j4 + i] = v;
            }
        }
        __syncthreads();
#pragma unroll
        for (int k = 0; k < 16; k++) {
            float4 b = *(const float4*)&sB[k][tx * 4];
            float4 a0 = *(const float4*)&sA[k][ty * 8];
            float4 a1 = *(const float4*)&sA[k][ty * 8 + 4];
            float ar[8] = {a0.x, a0.y, a0.z, a0.w, a1.x, a1.y, a1.z, a1.w};
#pragma unroll
            for (int r = 0; r < 8; r++) {
                acc[r][0] = fmaf(ar[r], b.x, acc[r][0]);
                acc[r][1] = fmaf(ar[r], b.y, acc[r][1]);
                acc[r][2] = fmaf(ar[r], b.z, acc[r][2]);
                acc[r][3] = fmaf(ar[r], b.w, acc[r][3]);
            }
        }
        __syncthreads();
    }

    float4 bv = make_float4(0.f, 0.f, 0.f, 0.f);
    if (bias) bv = *(const float4*)(bias + col0 + tx * 4);
#pragma unroll
    for (int r = 0; r < 8; r++) {
        int gr = row0 + ty * 8 + r;
        if (gr < NN) {
            float4 o = make_float4(acc[r][0] + bv.x, acc[r][1] + bv.y,
                                   acc[r][2] + bv.z, acc[r][3] + bv.w);
            if (POSTL) { o.x = lky(o.x); o.y = lky(o.y); o.z = lky(o.z); o.w = lky(o.w); }
            *(float4*)(C + (size_t)gr * J + col0 + tx * 4) = o;
        }
    }
}

// ---------------- fused gather + update, vectorized + 2x unrolled edge loop ----------------
// lane owns j = lane*V .. lane*V+V-1 ; per-j accumulation order = CSR edge order (unchanged)
template<int H, int RS>
__global__ void __launch_bounds__(256) k_gather_update(float* __restrict__ h,
                                                       const float* __restrict__ buf,
                                                       const float* __restrict__ bias) {
    int node = (blockIdx.x * blockDim.x + threadIdx.x) >> 5;
    if (node >= NN) return;
    int lane = threadIdx.x & 31;
    constexpr int V = H / 32;       // 4 (H=128) or 2 (H=64)
    float di = g_dinv[node];
    const float* mr = buf + (size_t)node * RS + lane * V;
    float acc[V];
#pragma unroll
    for (int c = 0; c < V; c++)
        acc[c] = mr[c] * di * di;   // self loop
    int e0 = g_rowptr[node], e1 = g_rowptr[node + 1];
    int e = e0;
    for (; e + 1 < e1; e += 2) {
        int s0 = g_colidx[e], s1 = g_colidx[e + 1];
        float w0 = g_dinv[s0] * di, w1 = g_dinv[s1] * di;
        const float* m0 = buf + (size_t)s0 * RS + lane * V;
        const float* m1 = buf + (size_t)s1 * RS + lane * V;
        if (V == 4) {
            float4 v0 = *(const float4*)m0;
            float4 v1 = *(const float4*)m1;
            acc[0] = fmaf(v1.x, w1, fmaf(v0.x, w0, acc[0]));
            acc[1] = fmaf(v1.y, w1, fmaf(v0.y, w0, acc[1]));
            acc[2] = fmaf(v1.z, w1, fmaf(v0.z, w0, acc[2]));
            acc[3] = fmaf(v1.w, w1, fmaf(v0.w, w0, acc[3]));
        } else {
            float2 v0 = *(const float2*)m0;
            float2 v1 = *(const float2*)m1;
            acc[0] = fmaf(v1.x, w1, fmaf(v0.x, w0, acc[0]));
            acc[1] = fmaf(v1.y, w1, fmaf(v0.y, w0, acc[1]));
        }
    }
    if (e < e1) {
        int s0 = g_colidx[e];
        float w0 = g_dinv[s0] * di;
        const float* m0 = buf + (size_t)s0 * RS + lane * V;
        if (V == 4) {
            float4 v0 = *(const float4*)m0;
            acc[0] = fmaf(v0.x, w0, acc[0]);
            acc[1] = fmaf(v0.y, w0, acc[1]);
            acc[2] = fmaf(v0.z, w0, acc[2]);
            acc[3] = fmaf(v0.w, w0, acc[3]);
        } else {
            float2 v0 = *(const float2*)m0;
            acc[0] = fmaf(v0.x, w0, acc[0]);
            acc[1] = fmaf(v0.y, w0, acc[1]);
        }
    }
#pragma unroll
    for (int c = 0; c < V; c++) {
        int j = lane * V + c;
        float anti = mr[H];                     // placeholder; real read below
        (void)anti;
        float a = buf[(size_t)node * RS + H + j];   // anti half (includes -gamma*h)
        size_t idx = (size_t)node * H + j;
        h[idx] += EPS_C * tanhf(a + acc[c] + bias[j]);
    }
}

// ---------------- fc + log_softmax, thread per node, unrolled ----------------
__global__ void k_fc(const float* __restrict__ h2, const float* __restrict__ wfc,
                     const float* __restrict__ bfc, float* __restrict__ out) {
    int i = blockIdx.x * blockDim.x + threadIdx.x;
    if (i >= NN) return;
    float hv[64];
    const float* hr = h2 + (size_t)i * 64;
#pragma unroll
    for (int k = 0; k < 64; k++) hv[k] = hr[k];
    float lg[40];
    float m = -1e30f;
#pragma unroll 4
    for (int j = 0; j < 40; j++) {
        float acc = bfc[j];
#pragma unroll
        for (int k = 0; k < 64; k++)
            acc += hv[k] * wfc[(size_t)j * 64 + k];
        lg[j] = acc;
        m = fmaxf(m, acc);
    }
    float s = 0.f;
#pragma unroll 8
    for (int j = 0; j < 40; j++) s += expf(lg[j] - m);
    float lse = m + logf(s);
    float* o = out + (size_t)i * 40;
#pragma unroll 8
    for (int j = 0; j < 40; j++) o[j] = lg[j] - lse;
}

// ---------------- launch: layer0 GEMM moved to position #4 for ncu capture ----------------
extern "C" void kernel_launch(void* const* d_in, const int* in_sizes, int n_in,
                              void* d_out, int out_size) {
    const float* x      = (const float*)d_in[0];
    const void*  edges  = d_in[1];
    const float* w_hid  = (const float*)d_in[2];
    const float* b_hid  = (const float*)d_in[3];
    const float* W_a1   = (const float*)d_in[4];
    const float* gcn_w1 = (const float*)d_in[5];
    const float* b_a1   = (const float*)d_in[6];
    const float* w_hid2 = (const float*)d_in[7];
    const float* b_hid2 = (const float*)d_in[8];
    const float* W_a2   = (const float*)d_in[9];
    const float* gcn_w2 = (const float*)d_in[10];
    const float* b_a2   = (const float*)d_in[11];
    const float* w_fc   = (const float*)d_in[12];
    const float* b_fc   = (const float*)d_in[13];
    float* out = (float*)d_out;

    int gx = (NN + 127) / 128;
    int nodeWarps = (NN * 32 + 255) / 256;
    int cvtBlocks = ((EE > NN ? EE : NN) + 255) / 256;

    // #1..#3: minimal prerequisites
    probe_kernel<<<1, 1024>>>((const unsigned int*)edges);
    convert_zero<<<cvtBlocks, 256>>>(edges);
    hist_kernel<<<(EE + 255) / 256, 256>>>();

    // #4: layer0 GEMM  (target of the ncu single-launch capture)
    gemm_kernel<256, 128, 0, 0, 1><<<dim3(gx, 2), 256>>>(x, w_hid, nullptr, b_hid, g_h);

    // rest of preprocessing (needed before first gather)
    dinv_kernel<<<(NN + 255) / 256, 256>>>();
    scan_kernel<<<1, 1024>>>();
    cursor_copy<<<(NN + 255) / 256, 256>>>();
    fill_kernel<<<(EE + 255) / 256, 256>>>();

    // conv1: 3 iterations, H=128
    for (int it = 0; it < 3; it++) {
        gemm_kernel<128, 256, 1, 0, 0><<<dim3(gx, 4), 256>>>(g_h, gcn_w1, W_a1, nullptr, g_buf);
        k_gather_update<128, 256><<<nodeWarps, 256>>>(g_h, g_buf, b_a1);
    }

    // hid2
    gemm_kernel<128, 64, 0, 1, 1><<<dim3(gx, 1), 256>>>(g_h, w_hid2, nullptr, b_hid2, g_h2);

    // conv2: 1 iteration, H=64
    gemm_kernel<64, 128, 1, 0, 0><<<dim3(gx, 2), 256>>>(g_h2, gcn_w2, W_a2, nullptr, g_buf);
    k_gather_update<64, 128><<<nodeWarps, 256>>>(g_h2, g_buf, b_a2);

    // fc + log_softmax
    k_fc<<<(NN + 255) / 256, 256>>>(g_h2, w_fc, b_fc, out);
}

// round 11
// speedup vs baseline: 1.0726x; 1.0726x over previous
#include <cuda_runtime.h>
#include <math.h>

#define LEAKY_SLOPE 0.01f
#define EPS_C 0.1f
#define GAMMA_C 0.1f

#define NN 50000
#define EE 600000

// ---------------- scratch (node/edge data only; NO weight-copy arrays) ----------------
__device__ __align__(16) float g_h   [NN * 128];
__device__ __align__(16) float g_h2  [NN * 64];
__device__ __align__(16) float g_buf [NN * 256];   // fused [msg | anti] rows
__device__ int   g_deg   [NN];
__device__ float g_dinv  [NN];
__device__ int   g_src   [EE];
__device__ int   g_dst   [EE];
__device__ int   g_rowptr[NN + 1];
__device__ int   g_cursor[NN];
__device__ int   g_colidx[EE];
__device__ int   g_is64;

__device__ __forceinline__ float lky(float x) { return x > 0.f ? x : LEAKY_SLOPE * x; }
__device__ __forceinline__ int clampN(int v) { return v < 0 ? 0 : (v >= NN ? NN - 1 : v); }

// ---------------- probe (launch #1) ----------------
__global__ void probe_kernel(const unsigned int* __restrict__ w) {
    __shared__ int fl;
    if (threadIdx.x == 0) fl = 0;
    __syncthreads();
    for (int i = 1 + 2 * (int)threadIdx.x; i < 16384; i += 2 * (int)blockDim.x)
        if (w[i] != 0u) fl = 1;
    __syncthreads();
    if (threadIdx.x == 0) g_is64 = (fl == 0) ? 1 : 0;
}

// ---------------- convert + zero_deg fused (launch #2) ----------------
__global__ void convert_zero(const void* __restrict__ raw) {
    int i = blockIdx.x * blockDim.x + threadIdx.x;
    if (i < NN) g_deg[i] = 0;
    if (i >= EE) return;
    int s, d;
    if (g_is64) {
        const long long* p = (const long long*)raw;
        s = (int)p[i];
        d = (int)p[EE + i];
    } else {
        const int* p = (const int*)raw;
        s = p[i];
        d = p[EE + i];
    }
    g_src[i] = clampN(s);
    g_dst[i] = clampN(d);
}

// ---------------- hist (launch #3) ----------------
__global__ void hist_kernel() {
    int i = blockIdx.x * blockDim.x + threadIdx.x;
    if (i < EE) atomicAdd(&g_deg[g_dst[i]], 1);
}

// ---------------- degree norm ----------------
__global__ void dinv_kernel() {
    int i = blockIdx.x * blockDim.x + threadIdx.x;
    if (i < NN) g_dinv[i] = rsqrtf((float)(g_deg[i] + 1));  // +1 self loop
}

// ---------------- CSR scan (writes rowptr AND cursor) ----------------
__global__ void scan_kernel() {
    __shared__ int sh[1024];
    __shared__ int carry;
    int t = threadIdx.x;
    if (t == 0) carry = 0;
    __syncthreads();
    for (int base = 0; base < NN; base += 1024) {
        int v = (base + t < NN) ? g_deg[base + t] : 0;
        sh[t] = v;
        __syncthreads();
        for (int off = 1; off < 1024; off <<= 1) {
            int add = (t >= off) ? sh[t - off] : 0;
            __syncthreads();
            sh[t] += add;
            __syncthreads();
        }
        int incl = sh[t];
        int excl = carry + incl - v;
        if (base + t < NN) {
            g_rowptr[base + t] = excl;
            g_cursor[base + t] = excl;
        }
        __syncthreads();
        if (t == 1023) carry += incl;
        __syncthreads();
    }
    if (t == 0) g_rowptr[NN] = carry;
}
__global__ void fill_kernel() {
    int i = blockIdx.x * blockDim.x + threadIdx.x;
    if (i >= EE) return;
    int d = g_dst[i];
    int p = atomicAdd(&g_cursor[d], 1);
    if (p < EE) g_colidx[p] = g_src[i];
}

// ---------------- tiled GEMM v2: 128x(BN) tile, 8x(BN/16)/thread, raw-weight B tiles --------
// C[i][j] = postAct( preAct(A[i]) @ B + bias )
// BMODE 0: B[k][j] = W1[j*K + k]
// BMODE 1: j < J/2 : B[k][j] = W1[k*(J/2) + j]
//          j >= J/2: B[k][j] = W2[jj*(J/2)+k] - W2[k*(J/2)+jj] - (k==jj)*gamma
template<int K, int J, int BN, int BMODE, int PREL, int POSTL>
__global__ void __launch_bounds__(256)
gemm_kernel(const float* __restrict__ A, const float* __restrict__ W1,
            const float* __restrict__ W2, const float* __restrict__ bias,
            float* __restrict__ C) {
    constexpr int TN = BN / 16;              // cols per thread (8 or 4)
    __shared__ float sA[16][128 + 4];
    __shared__ float sB[16][BN];
    int tid = threadIdx.x;
    int tx = tid & 15;                       // col group
    int ty = tid >> 4;                       // row group (0..15), 8 rows each
    int row0 = blockIdx.x * 128;
    int col0 = blockIdx.y * BN;
    constexpr int HALF = J / 2;

    float acc[8][TN];
#pragma unroll
    for (int r = 0; r < 8; r++)
#pragma unroll
        for (int c = 0; c < TN; c++) acc[r][c] = 0.f;

    for (int kt = 0; kt < K; kt += 16) {
        // ---- A tile: 128 rows x 16 k, transposed into sA[k][row] ----
#pragma unroll
        for (int li = 0; li < 2; li++) {
            int idx = tid + li * 256;
            int r = idx >> 2;
            int k4 = (idx & 3) * 4;
            float4 v = make_float4(0.f, 0.f, 0.f, 0.f);
            int gr = row0 + r;
            if (gr < NN) v = *(const float4*)(A + (size_t)gr * K + kt + k4);
            if (PREL) { v.x = lky(v.x); v.y = lky(v.y); v.z = lky(v.z); v.w = lky(v.w); }
            sA[k4 + 0][r] = v.x;
            sA[k4 + 1][r] = v.y;
            sA[k4 + 2][r] = v.z;
            sA[k4 + 3][r] = v.w;
        }
        // ---- B tile: 16 k x BN j ----
        if (BMODE == 0) {
            // thread loads a run of k for one j (coalesced along W1 rows)
            constexpr int TPJ = 256 / BN;          // threads per j (2 or 4)
            constexpr int KRUN = 16 / TPJ;         // k per thread (8 or 4)
            int jloc = tid / TPJ;
            int kloc = (tid % TPJ) * KRUN;
            int j = col0 + jloc;
            const float* wp = W1 + (size_t)j * K + kt + kloc;
#pragma unroll
            for (int q = 0; q < KRUN; q += 4) {
                float4 v = *(const float4*)(wp + q);
                sB[kloc + q + 0][jloc] = v.x;
                sB[kloc + q + 1][jloc] = v.y;
                sB[kloc + q + 2][jloc] = v.z;
                sB[kloc + q + 3][jloc] = v.w;
            }
        } else {
            int k = tid >> 4;
            int j4 = (tid & 15) * TN;
            int kk = kt + k;
#pragma unroll
            for (int i = 0; i < TN; i++) {
                int j = col0 + j4 + i;
                float v;
                if (j < HALF) {
                    v = W1[(size_t)kk * HALF + j];
                } else {
                    int jj = j - HALF;
                    v = W2[(size_t)jj * HALF + kk] - W2[(size_t)kk * HALF + jj]
                        - ((kk == jj) ? GAMMA_C : 0.f);
                }
                sB[k][j4 + i] = v;
            }
        }
        __syncthreads();
#pragma unroll
        for (int k = 0; k < 16; k++) {
            float a0[8];
            float4 va = *(const float4*)&sA[k][ty * 8];
            float4 vb = *(const float4*)&sA[k][ty * 8 + 4];
            a0[0] = va.x; a0[1] = va.y; a0[2] = va.z; a0[3] = va.w;
            a0[4] = vb.x; a0[5] = vb.y; a0[6] = vb.z; a0[7] = vb.w;
            float bb[TN];
#pragma unroll
            for (int c = 0; c < TN; c += 4) {
                float4 v = *(const float4*)&sB[k][tx * TN + c];
                bb[c + 0] = v.x; bb[c + 1] = v.y; bb[c + 2] = v.z; bb[c + 3] = v.w;
            }
#pragma unroll
            for (int r = 0; r < 8; r++)
#pragma unroll
                for (int c = 0; c < TN; c++)
                    acc[r][c] = fmaf(a0[r], bb[c], acc[r][c]);
        }
        __syncthreads();
    }

    float bv[TN];
#pragma unroll
    for (int c = 0; c < TN; c++) bv[c] = bias ? bias[col0 + tx * TN + c] : 0.f;
#pragma unroll
    for (int r = 0; r < 8; r++) {
        int gr = row0 + ty * 8 + r;
        if (gr < NN) {
#pragma unroll
            for (int c = 0; c < TN; c += 4) {
                float4 o;
                o.x = acc[r][c + 0] + bv[c + 0];
                o.y = acc[r][c + 1] + bv[c + 1];
                o.z = acc[r][c + 2] + bv[c + 2];
                o.w = acc[r][c + 3] + bv[c + 3];
                if (POSTL) { o.x = lky(o.x); o.y = lky(o.y); o.z = lky(o.z); o.w = lky(o.w); }
                *(float4*)(C + (size_t)gr * J + col0 + tx * TN + c) = o;
            }
        }
    }
}

// ---------------- fused gather + update, vectorized (R10, cleaned) ----------------
template<int H, int RS>
__global__ void __launch_bounds__(256) k_gather_update(float* __restrict__ h,
                                                       const float* __restrict__ buf,
                                                       const float* __restrict__ bias) {
    int node = (blockIdx.x * blockDim.x + threadIdx.x) >> 5;
    if (node >= NN) return;
    int lane = threadIdx.x & 31;
    constexpr int V = H / 32;       // 4 (H=128) or 2 (H=64)
    float di = g_dinv[node];
    const float* mr = buf + (size_t)node * RS + lane * V;
    float acc[V];
#pragma unroll
    for (int c = 0; c < V; c++)
        acc[c] = mr[c] * di * di;   // self loop
    int e0 = g_rowptr[node], e1 = g_rowptr[node + 1];
    int e = e0;
    for (; e + 1 < e1; e += 2) {
        int s0 = g_colidx[e], s1 = g_colidx[e + 1];
        float w0 = g_dinv[s0] * di, w1 = g_dinv[s1] * di;
        const float* m0 = buf + (size_t)s0 * RS + lane * V;
        const float* m1 = buf + (size_t)s1 * RS + lane * V;
        if (V == 4) {
            float4 v0 = *(const float4*)m0;
            float4 v1 = *(const float4*)m1;
            acc[0] = fmaf(v1.x, w1, fmaf(v0.x, w0, acc[0]));
            acc[1] = fmaf(v1.y, w1, fmaf(v0.y, w0, acc[1]));
            acc[2] = fmaf(v1.z, w1, fmaf(v0.z, w0, acc[2]));
            acc[3] = fmaf(v1.w, w1, fmaf(v0.w, w0, acc[3]));
        } else {
            float2 v0 = *(const float2*)m0;
            float2 v1 = *(const float2*)m1;
            acc[0] = fmaf(v1.x, w1, fmaf(v0.x, w0, acc[0]));
            acc[1] = fmaf(v1.y, w1, fmaf(v0.y, w0, acc[1]));
        }
    }
    if (e < e1) {
        int s0 = g_colidx[e];
        float w0 = g_dinv[s0] * di;
        const float* m0 = buf + (size_t)s0 * RS + lane * V;
        if (V == 4) {
            float4 v0 = *(const float4*)m0;
            acc[0] = fmaf(v0.x, w0, acc[0]);
            acc[1] = fmaf(v0.y, w0, acc[1]);
            acc[2] = fmaf(v0.z, w0, acc[2]);
            acc[3] = fmaf(v0.w, w0, acc[3]);
        } else {
            float2 v0 = *(const float2*)m0;
            acc[0] = fmaf(v0.x, w0, acc[0]);
            acc[1] = fmaf(v0.y, w0, acc[1]);
        }
    }
#pragma unroll
    for (int c = 0; c < V; c++) {
        int j = lane * V + c;
        float a = buf[(size_t)node * RS + H + j];   // anti half (includes -gamma*h)
        size_t idx = (size_t)node * H + j;
        h[idx] += EPS_C * tanhf(a + acc[c] + bias[j]);
    }
}

// ---------------- fc + log_softmax, thread per node (plain R9 version) ----------------
__global__ void k_fc(const float* __restrict__ h2, const float* __restrict__ wfc,
                     const float* __restrict__ bfc, float* __restrict__ out) {
    int i = blockIdx.x * blockDim.x + threadIdx.x;
    if (i >= NN) return;
    float hv[64];
    const float* hr = h2 + (size_t)i * 64;
    for (int k = 0; k < 64; k++) hv[k] = hr[k];
    float lg[40];
    float m = -1e30f;
    for (int j = 0; j < 40; j++) {
        float acc = bfc[j];
        for (int k = 0; k < 64; k++)
            acc += hv[k] * wfc[(size_t)j * 64 + k];
        lg[j] = acc;
        m = fmaxf(m, acc);
    }
    float s = 0.f;
    for (int j = 0; j < 40; j++) s += expf(lg[j] - m);
    float lse = m + logf(s);
    float* o = out + (size_t)i * 40;
    for (int j = 0; j < 40; j++) o[j] = lg[j] - lse;
}

// ---------------- launch (layer0 GEMM stays at slot #4 for ncu capture) ----------------
extern "C" void kernel_launch(void* const* d_in, const int* in_sizes, int n_in,
                              void* d_out, int out_size) {
    const float* x      = (const float*)d_in[0];
    const void*  edges  = d_in[1];
    const float* w_hid  = (const float*)d_in[2];
    const float* b_hid  = (const float*)d_in[3];
    const float* W_a1   = (const float*)d_in[4];
    const float* gcn_w1 = (const float*)d_in[5];
    const float* b_a1   = (const float*)d_in[6];
    const float* w_hid2 = (const float*)d_in[7];
    const float* b_hid2 = (const float*)d_in[8];
    const float* W_a2   = (const float*)d_in[9];
    const float* gcn_w2 = (const float*)d_in[10];
    const float* b_a2   = (const float*)d_in[11];
    const float* w_fc   = (const float*)d_in[12];
    const float* b_fc   = (const float*)d_in[13];
    float* out = (float*)d_out;

    int gx = (NN + 127) / 128;                 // 391
    int nodeWarps = (NN * 32 + 255) / 256;
    int cvtBlocks = ((EE > NN ? EE : NN) + 255) / 256;

    // #1..#3
    probe_kernel<<<1, 1024>>>((const unsigned int*)edges);
    convert_zero<<<cvtBlocks, 256>>>(edges);
    hist_kernel<<<(EE + 255) / 256, 256>>>();

    // #4: layer0 GEMM  [N,256]->[N,128]   (ncu capture target)
    gemm_kernel<256, 128, 128, 0, 0, 1><<<dim3(gx, 1), 256>>>(x, w_hid, nullptr, b_hid, g_h);

    // rest of preprocessing
    dinv_kernel<<<(NN + 255) / 256, 256>>>();
    scan_kernel<<<1, 1024>>>();
    fill_kernel<<<(EE + 255) / 256, 256>>>();

    // conv1: 3 iterations, H=128
    for (int it = 0; it < 3; it++) {
        gemm_kernel<128, 256, 128, 1, 0, 0><<<dim3(gx, 2), 256>>>(g_h, gcn_w1, W_a1, nullptr, g_buf);
        k_gather_update<128, 256><<<nodeWarps, 256>>>(g_h, g_buf, b_a1);
    }

    // hid2  [N,128]->[N,64]
    gemm_kernel<128, 64, 64, 0, 1, 1><<<dim3(gx, 1), 256>>>(g_h, w_hid2, nullptr, b_hid2, g_h2);

    // conv2: 1 iteration, H=64
    gemm_kernel<64, 128, 128, 1, 0, 0><<<dim3(gx, 1), 256>>>(g_h2, gcn_w2, W_a2, nullptr, g_buf);
    k_gather_update<64, 128><<<nodeWarps, 256>>>(g_h2, g_buf, b_a2);

    // fc + log_softmax
    k_fc<<<(NN + 255) / 256, 256>>>(g_h2, w_fc, b_fc, out);
}

// round 12
// speedup vs baseline: 1.1501x; 1.0723x over previous
#include <cuda_runtime.h>
#include <math.h>

#define LEAKY_SLOPE 0.01f
#define EPS_C 0.1f
#define GAMMA_C 0.1f

#define NN 50000
#define EE 600000

// ---------------- scratch (node/edge data only; NO weight-copy arrays) ----------------
__device__ __align__(16) float g_h   [NN * 128];
__device__ __align__(16) float g_h2  [NN * 64];
__device__ __align__(16) float g_buf [NN * 256];   // fused [msg | anti] rows
__device__ int   g_deg   [NN];
__device__ float g_dinv  [NN];
__device__ int   g_src   [EE];
__device__ int   g_dst   [EE];
__device__ int   g_rowptr[NN + 1];
__device__ int   g_cursor[NN];
__device__ int   g_colidx[EE];
__device__ int   g_is64;

__device__ __forceinline__ float lky(float x) { return x > 0.f ? x : LEAKY_SLOPE * x; }
__device__ __forceinline__ int clampN(int v) { return v < 0 ? 0 : (v >= NN ? NN - 1 : v); }

// ---------------- probe (launch #1) ----------------
__global__ void probe_kernel(const unsigned int* __restrict__ w) {
    __shared__ int fl;
    if (threadIdx.x == 0) fl = 0;
    __syncthreads();
    for (int i = 1 + 2 * (int)threadIdx.x; i < 16384; i += 2 * (int)blockDim.x)
        if (w[i] != 0u) fl = 1;
    __syncthreads();
    if (threadIdx.x == 0) g_is64 = (fl == 0) ? 1 : 0;
}

// ---------------- convert + zero_deg fused (launch #2) ----------------
__global__ void convert_zero(const void* __restrict__ raw) {
    int i = blockIdx.x * blockDim.x + threadIdx.x;
    if (i < NN) g_deg[i] = 0;
    if (i >= EE) return;
    int s, d;
    if (g_is64) {
        const long long* p = (const long long*)raw;
        s = (int)p[i];
        d = (int)p[EE + i];
    } else {
        const int* p = (const int*)raw;
        s = p[i];
        d = p[EE + i];
    }
    g_src[i] = clampN(s);
    g_dst[i] = clampN(d);
}

// ---------------- hist (launch #3) ----------------
__global__ void hist_kernel() {
    int i = blockIdx.x * blockDim.x + threadIdx.x;
    if (i < EE) atomicAdd(&g_deg[g_dst[i]], 1);
}

// ---------------- degree norm ----------------
__global__ void dinv_kernel() {
    int i = blockIdx.x * blockDim.x + threadIdx.x;
    if (i < NN) g_dinv[i] = rsqrtf((float)(g_deg[i] + 1));  // +1 self loop
}

// ---------------- CSR scan (writes rowptr AND cursor) ----------------
__global__ void scan_kernel() {
    __shared__ int sh[1024];
    __shared__ int carry;
    int t = threadIdx.x;
    if (t == 0) carry = 0;
    __syncthreads();
    for (int base = 0; base < NN; base += 1024) {
        int v = (base + t < NN) ? g_deg[base + t] : 0;
        sh[t] = v;
        __syncthreads();
        for (int off = 1; off < 1024; off <<= 1) {
            int add = (t >= off) ? sh[t - off] : 0;
            __syncthreads();
            sh[t] += add;
            __syncthreads();
        }
        int incl = sh[t];
        int excl = carry + incl - v;
        if (base + t < NN) {
            g_rowptr[base + t] = excl;
            g_cursor[base + t] = excl;
        }
        __syncthreads();
        if (t == 1023) carry += incl;
        __syncthreads();
    }
    if (t == 0) g_rowptr[NN] = carry;
}
__global__ void fill_kernel() {
    int i = blockIdx.x * blockDim.x + threadIdx.x;
    if (i >= EE) return;
    int d = g_dst[i];
    int p = atomicAdd(&g_cursor[d], 1);
    if (p < EE) g_colidx[p] = g_src[i];
}

// ---------------- GEMM v3: 128x64 tile, 8x4/thread, double-buffered smem ----------------
// C[i][j] = postAct( preAct(A[i]) @ B + bias )
// BMODE 0: B[k][j] = W1[j*K + k]
// BMODE 1: j < J/2 : B[k][j] = W1[k*(J/2) + j]
//          j >= J/2: B[k][j] = W2[jj*(J/2)+k] - W2[k*(J/2)+jj] - (k==jj)*gamma
template<int K, int J, int BMODE, int PREL, int POSTL>
__global__ void __launch_bounds__(256)
gemm_kernel(const float* __restrict__ A, const float* __restrict__ W1,
            const float* __restrict__ W2, const float* __restrict__ bias,
            float* __restrict__ C) {
    __shared__ float sA[2][16][132];
    __shared__ float sB[2][16][64];
    const int tid = threadIdx.x;
    const int tx = tid & 15;
    const int ty = tid >> 4;
    const int row0 = blockIdx.x * 128;
    const int col0 = blockIdx.y * 64;
    constexpr int HALF = J / 2;
    constexpr int NT = K / 16;

    // A staging: idx = tid + li*256 -> r = idx>>2, k4 = (tid&3)*4
    const int ar0 = tid >> 2;
    const int ak4 = (tid & 3) * 4;
    // BMODE0 B staging: 4 threads per j, float4 along k
    const int jloc0 = tid >> 2;          // 0..63
    const int kloc0 = (tid & 3) * 4;     // 0,4,8,12
    // BMODE1 B staging: float4 along j
    const int kB1 = tid >> 4;            // 0..15
    const int jB1 = (tid & 15) * 4;      // 0..60

    float4 stA0, stA1, stB;

    float acc[8][4];
#pragma unroll
    for (int r = 0; r < 8; r++)
#pragma unroll
        for (int c = 0; c < 4; c++) acc[r][c] = 0.f;

    // ---- prefetch tile kt into staging regs ----
    auto prefetch = [&](int kt) {
        {
            float4 v = make_float4(0.f, 0.f, 0.f, 0.f);
            int gr = row0 + ar0;
            if (gr < NN) v = *(const float4*)(A + (size_t)gr * K + kt + ak4);
            if (PREL) { v.x = lky(v.x); v.y = lky(v.y); v.z = lky(v.z); v.w = lky(v.w); }
            stA0 = v;
        }
        {
            float4 v = make_float4(0.f, 0.f, 0.f, 0.f);
            int gr = row0 + ar0 + 64;
            if (gr < NN) v = *(const float4*)(A + (size_t)gr * K + kt + ak4);
            if (PREL) { v.x = lky(v.x); v.y = lky(v.y); v.z = lky(v.z); v.w = lky(v.w); }
            stA1 = v;
        }
        if (BMODE == 0) {
            int j = col0 + jloc0;
            stB = *(const float4*)(W1 + (size_t)j * K + kt + kloc0);
        } else {
            int kk = kt + kB1;
            float b[4];
#pragma unroll
            for (int i = 0; i < 4; i++) {
                int j = col0 + jB1 + i;
                if (j < HALF) {
                    b[i] = W1[(size_t)kk * HALF + j];
                } else {
                    int jj = j - HALF;
                    b[i] = W2[(size_t)jj * HALF + kk] - W2[(size_t)kk * HALF + jj]
                         - ((kk == jj) ? GAMMA_C : 0.f);
                }
            }
            stB = make_float4(b[0], b[1], b[2], b[3]);
        }
    };
    // ---- commit staging regs into smem buffer ----
    auto commit = [&](int buf) {
        sA[buf][ak4 + 0][ar0] = stA0.x;
        sA[buf][ak4 + 1][ar0] = stA0.y;
        sA[buf][ak4 + 2][ar0] = stA0.z;
        sA[buf][ak4 + 3][ar0] = stA0.w;
        sA[buf][ak4 + 0][ar0 + 64] = stA1.x;
        sA[buf][ak4 + 1][ar0 + 64] = stA1.y;
        sA[buf][ak4 + 2][ar0 + 64] = stA1.z;
        sA[buf][ak4 + 3][ar0 + 64] = stA1.w;
        if (BMODE == 0) {
            sB[buf][kloc0 + 0][jloc0] = stB.x;
            sB[buf][kloc0 + 1][jloc0] = stB.y;
            sB[buf][kloc0 + 2][jloc0] = stB.z;
            sB[buf][kloc0 + 3][jloc0] = stB.w;
        } else {
            *(float4*)&sB[buf][kB1][jB1] = stB;
        }
    };

    prefetch(0);
    commit(0);
    __syncthreads();

    int cur = 0;
#pragma unroll 1
    for (int t = 0; t < NT; t++) {
        if (t + 1 < NT) prefetch((t + 1) * 16);
#pragma unroll
        for (int k = 0; k < 16; k++) {
            float4 va = *(const float4*)&sA[cur][k][ty * 8];
            float4 vb = *(const float4*)&sA[cur][k][ty * 8 + 4];
            float4 bb = *(const float4*)&sB[cur][k][tx * 4];
            float a0[8] = {va.x, va.y, va.z, va.w, vb.x, vb.y, vb.z, vb.w};
#pragma unroll
            for (int r = 0; r < 8; r++) {
                acc[r][0] = fmaf(a0[r], bb.x, acc[r][0]);
                acc[r][1] = fmaf(a0[r], bb.y, acc[r][1]);
                acc[r][2] = fmaf(a0[r], bb.z, acc[r][2]);
                acc[r][3] = fmaf(a0[r], bb.w, acc[r][3]);
            }
        }
        if (t + 1 < NT) {
            commit(cur ^ 1);
            __syncthreads();
            cur ^= 1;
        }
    }

    float4 bv = make_float4(0.f, 0.f, 0.f, 0.f);
    if (bias) bv = *(const float4*)(bias + col0 + tx * 4);
#pragma unroll
    for (int r = 0; r < 8; r++) {
        int gr = row0 + ty * 8 + r;
        if (gr < NN) {
            float4 o = make_float4(acc[r][0] + bv.x, acc[r][1] + bv.y,
                                   acc[r][2] + bv.z, acc[r][3] + bv.w);
            if (POSTL) { o.x = lky(o.x); o.y = lky(o.y); o.z = lky(o.z); o.w = lky(o.w); }
            *(float4*)(C + (size_t)gr * J + col0 + tx * 4) = o;
        }
    }
}

// ---------------- fused gather + update, vectorized (verbatim R11) ----------------
template<int H, int RS>
__global__ void __launch_bounds__(256) k_gather_update(float* __restrict__ h,
                                                       const float* __restrict__ buf,
                                                       const float* __restrict__ bias) {
    int node = (blockIdx.x * blockDim.x + threadIdx.x) >> 5;
    if (node >= NN) return;
    int lane = threadIdx.x & 31;
    constexpr int V = H / 32;       // 4 (H=128) or 2 (H=64)
    float di = g_dinv[node];
    const float* mr = buf + (size_t)node * RS + lane * V;
    float acc[V];
#pragma unroll
    for (int c = 0; c < V; c++)
        acc[c] = mr[c] * di * di;   // self loop
    int e0 = g_rowptr[node], e1 = g_rowptr[node + 1];
    int e = e0;
    for (; e + 1 < e1; e += 2) {
        int s0 = g_colidx[e], s1 = g_colidx[e + 1];
        float w0 = g_dinv[s0] * di, w1 = g_dinv[s1] * di;
        const float* m0 = buf + (size_t)s0 * RS + lane * V;
        const float* m1 = buf + (size_t)s1 * RS + lane * V;
        if (V == 4) {
            float4 v0 = *(const float4*)m0;
            float4 v1 = *(const float4*)m1;
            acc[0] = fmaf(v1.x, w1, fmaf(v0.x, w0, acc[0]));
            acc[1] = fmaf(v1.y, w1, fmaf(v0.y, w0, acc[1]));
            acc[2] = fmaf(v1.z, w1, fmaf(v0.z, w0, acc[2]));
            acc[3] = fmaf(v1.w, w1, fmaf(v0.w, w0, acc[3]));
        } else {
            float2 v0 = *(const float2*)m0;
            float2 v1 = *(const float2*)m1;
            acc[0] = fmaf(v1.x, w1, fmaf(v0.x, w0, acc[0]));
            acc[1] = fmaf(v1.y, w1, fmaf(v0.y, w0, acc[1]));
        }
    }
    if (e < e1) {
        int s0 = g_colidx[e];
        float w0 = g_dinv[s0] * di;
        const float* m0 = buf + (size_t)s0 * RS + lane * V;
        if (V == 4) {
            float4 v0 = *(const float4*)m0;
            acc[0] = fmaf(v0.x, w0, acc[0]);
            acc[1] = fmaf(v0.y, w0, acc[1]);
            acc[2] = fmaf(v0.z, w0, acc[2]);
            acc[3] = fmaf(v0.w, w0, acc[3]);
        } else {
            float2 v0 = *(const float2*)m0;
            acc[0] = fmaf(v0.x, w0, acc[0]);
            acc[1] = fmaf(v0.y, w0, acc[1]);
        }
    }
#pragma unroll
    for (int c = 0; c < V; c++) {
        int j = lane * V + c;
        float a = buf[(size_t)node * RS + H + j];   // anti half (includes -gamma*h)
        size_t idx = (size_t)node * H + j;
        h[idx] += EPS_C * tanhf(a + acc[c] + bias[j]);
    }
}

// ---------------- fc + log_softmax, thread per node (verbatim R11) ----------------
__global__ void k_fc(const float* __restrict__ h2, const float* __restrict__ wfc,
                     const float* __restrict__ bfc, float* __restrict__ out) {
    int i = blockIdx.x * blockDim.x + threadIdx.x;
    if (i >= NN) return;
    float hv[64];
    const float* hr = h2 + (size_t)i * 64;
    for (int k = 0; k < 64; k++) hv[k] = hr[k];
    float lg[40];
    float m = -1e30f;
    for (int j = 0; j < 40; j++) {
        float acc = bfc[j];
        for (int k = 0; k < 64; k++)
            acc += hv[k] * wfc[(size_t)j * 64 + k];
        lg[j] = acc;
        m = fmaxf(m, acc);
    }
    float s = 0.f;
    for (int j = 0; j < 40; j++) s += expf(lg[j] - m);
    float lse = m + logf(s);
    float* o = out + (size_t)i * 40;
    for (int j = 0; j < 40; j++) o[j] = lg[j] - lse;
}

// ---------------- launch (layer0 GEMM at capture slot #4) ----------------
extern "C" void kernel_launch(void* const* d_in, const int* in_sizes, int n_in,
                              void* d_out, int out_size) {
    const float* x      = (const float*)d_in[0];
    const void*  edges  = d_in[1];
    const float* w_hid  = (const float*)d_in[2];
    const float* b_hid  = (const float*)d_in[3];
    const float* W_a1   = (const float*)d_in[4];
    const float* gcn_w1 = (const float*)d_in[5];
    const float* b_a1   = (const float*)d_in[6];
    const float* w_hid2 = (const float*)d_in[7];
    const float* b_hid2 = (const float*)d_in[8];
    const float* W_a2   = (const float*)d_in[9];
    const float* gcn_w2 = (const float*)d_in[10];
    const float* b_a2   = (const float*)d_in[11];
    const float* w_fc   = (const float*)d_in[12];
    const float* b_fc   = (const float*)d_in[13];
    float* out = (float*)d_out;

    int gx = (NN + 127) / 128;                 // 391
    int nodeWarps = (NN * 32 + 255) / 256;
    int cvtBlocks = ((EE > NN ? EE : NN) + 255) / 256;

    // #1..#3
    probe_kernel<<<1, 1024>>>((const unsigned int*)edges);
    convert_zero<<<cvtBlocks, 256>>>(edges);
    hist_kernel<<<(EE + 255) / 256, 256>>>();

    // #4: layer0 GEMM  [N,256]->[N,128]   (ncu capture target)
    gemm_kernel<256, 128, 0, 0, 1><<<dim3(gx, 2), 256>>>(x, w_hid, nullptr, b_hid, g_h);

    // rest of preprocessing
    dinv_kernel<<<(NN + 255) / 256, 256>>>();
    scan_kernel<<<1, 1024>>>();
    fill_kernel<<<(EE + 255) / 256, 256>>>();

    // conv1: 3 iterations, H=128
    for (int it = 0; it < 3; it++) {
        gemm_kernel<128, 256, 1, 0, 0><<<dim3(gx, 4), 256>>>(g_h, gcn_w1, W_a1, nullptr, g_buf);
        k_gather_update<128, 256><<<nodeWarps, 256>>>(g_h, g_buf, b_a1);
    }

    // hid2  [N,128]->[N,64]
    gemm_kernel<128, 64, 0, 1, 1><<<dim3(gx, 1), 256>>>(g_h, w_hid2, nullptr, b_hid2, g_h2);

    // conv2: 1 iteration, H=64
    gemm_kernel<64, 128, 1, 0, 0><<<dim3(gx, 2), 256>>>(g_h2, gcn_w2, W_a2, nullptr, g_buf);
    k_gather_update<64, 128><<<nodeWarps, 256>>>(g_h2, g_buf, b_a2);

    // fc + log_softmax
    k_fc<<<(NN + 255) / 256, 256>>>(g_h2, w_fc, b_fc, out);
}

// round 13
// speedup vs baseline: 1.1638x; 1.0119x over previous
#include <cuda_runtime.h>
#include <math.h>

#define LEAKY_SLOPE 0.01f
#define EPS_C 0.1f
#define GAMMA_C 0.1f

#define NN 50000
#define EE 600000

// ---------------- scratch (node/edge data only; NO weight-copy arrays) ----------------
__device__ __align__(16) float g_h   [NN * 128];
__device__ __align__(16) float g_h2  [NN * 64];
__device__ __align__(16) float g_buf [NN * 256];   // fused [msg | anti] rows
__device__ int   g_deg   [NN];
__device__ float g_dinv  [NN];
__device__ int   g_src   [EE];
__device__ int   g_dst   [EE];
__device__ int   g_rowptr[NN + 1];
__device__ int   g_cursor[NN];
__device__ int   g_colidx[EE];
__device__ int   g_is64;

__device__ __forceinline__ float lky(float x) { return x > 0.f ? x : LEAKY_SLOPE * x; }
__device__ __forceinline__ int clampN(int v) { return v < 0 ? 0 : (v >= NN ? NN - 1 : v); }

// ---------------- packed fp32x2 helpers ----------------
__device__ __forceinline__ unsigned long long pk(float lo, float hi) {
    unsigned long long r;
    asm("mov.b64 %0, {%1,%2};" : "=l"(r) : "f"(lo), "f"(hi));
    return r;
}
__device__ __forceinline__ void upk(unsigned long long v, float& lo, float& hi) {
    asm("mov.b64 {%0,%1}, %2;" : "=f"(lo), "=f"(hi) : "l"(v));
}
// d += a*b lanewise; each lane is an exact fmaf (fp32) -> bitwise same as scalar path
__device__ __forceinline__ void fma2(unsigned long long& d, unsigned long long a,
                                     unsigned long long b) {
    asm("fma.rn.f32x2 %0, %1, %2, %0;" : "+l"(d) : "l"(a), "l"(b));
}

// ---------------- probe (launch #1) ----------------
__global__ void probe_kernel(const unsigned int* __restrict__ w) {
    __shared__ int fl;
    if (threadIdx.x == 0) fl = 0;
    __syncthreads();
    for (int i = 1 + 2 * (int)threadIdx.x; i < 16384; i += 2 * (int)blockDim.x)
        if (w[i] != 0u) fl = 1;
    __syncthreads();
    if (threadIdx.x == 0) g_is64 = (fl == 0) ? 1 : 0;
}

// ---------------- convert + zero_deg fused (launch #2) ----------------
__global__ void convert_zero(const void* __restrict__ raw) {
    int i = blockIdx.x * blockDim.x + threadIdx.x;
    if (i < NN) g_deg[i] = 0;
    if (i >= EE) return;
    int s, d;
    if (g_is64) {
        const long long* p = (const long long*)raw;
        s = (int)p[i];
        d = (int)p[EE + i];
    } else {
        const int* p = (const int*)raw;
        s = p[i];
        d = p[EE + i];
    }
    g_src[i] = clampN(s);
    g_dst[i] = clampN(d);
}

// ---------------- hist (launch #3) ----------------
__global__ void hist_kernel() {
    int i = blockIdx.x * blockDim.x + threadIdx.x;
    if (i < EE) atomicAdd(&g_deg[g_dst[i]], 1);
}

// ---------------- degree norm ----------------
__global__ void dinv_kernel() {
    int i = blockIdx.x * blockDim.x + threadIdx.x;
    if (i < NN) g_dinv[i] = rsqrtf((float)(g_deg[i] + 1));  // +1 self loop
}

// ---------------- CSR scan (writes rowptr AND cursor) ----------------
__global__ void scan_kernel() {
    __shared__ int sh[1024];
    __shared__ int carry;
    int t = threadIdx.x;
    if (t == 0) carry = 0;
    __syncthreads();
    for (int base = 0; base < NN; base += 1024) {
        int v = (base + t < NN) ? g_deg[base + t] : 0;
        sh[t] = v;
        __syncthreads();
        for (int off = 1; off < 1024; off <<= 1) {
            int add = (t >= off) ? sh[t - off] : 0;
            __syncthreads();
            sh[t] += add;
            __syncthreads();
        }
        int incl = sh[t];
        int excl = carry + incl - v;
        if (base + t < NN) {
            g_rowptr[base + t] = excl;
            g_cursor[base + t] = excl;
        }
        __syncthreads();
        if (t == 1023) carry += incl;
        __syncthreads();
    }
    if (t == 0) g_rowptr[NN] = carry;
}
__global__ void fill_kernel() {
    int i = blockIdx.x * blockDim.x + threadIdx.x;
    if (i >= EE) return;
    int d = g_dst[i];
    int p = atomicAdd(&g_cursor[d], 1);
    if (p < EE) g_colidx[p] = g_src[i];
}

// ---------------- GEMM v4: 128x64 tile, 8x4/thread, double-buffered smem, FFMA2 ----------
// C[i][j] = postAct( preAct(A[i]) @ B + bias )
// BMODE 0: B[k][j] = W1[j*K + k]
// BMODE 1: j < J/2 : B[k][j] = W1[k*(J/2) + j]
//          j >= J/2: B[k][j] = W2[jj*(J/2)+k] - W2[k*(J/2)+jj] - (k==jj)*gamma
template<int K, int J, int BMODE, int PREL, int POSTL>
__global__ void __launch_bounds__(256)
gemm_kernel(const float* __restrict__ A, const float* __restrict__ W1,
            const float* __restrict__ W2, const float* __restrict__ bias,
            float* __restrict__ C) {
    __shared__ float sA[2][16][132];
    __shared__ float sB[2][16][64];
    const int tid = threadIdx.x;
    const int tx = tid & 15;
    const int ty = tid >> 4;
    const int row0 = blockIdx.x * 128;
    const int col0 = blockIdx.y * 64;
    constexpr int HALF = J / 2;
    constexpr int NT = K / 16;

    const int ar0 = tid >> 2;
    const int ak4 = (tid & 3) * 4;
    const int jloc0 = tid >> 2;          // BMODE0: 0..63
    const int kloc0 = (tid & 3) * 4;     // BMODE0: 0,4,8,12
    const int kB1 = tid >> 4;            // BMODE1: 0..15
    const int jB1 = (tid & 15) * 4;      // BMODE1: 0..60

    float4 stA0, stA1, stB;

    // packed accumulators: acc[p][c] holds (row ty*8+2p, row ty*8+2p+1) for col tx*4+c
    unsigned long long acc[4][4];
#pragma unroll
    for (int p = 0; p < 4; p++)
#pragma unroll
        for (int c = 0; c < 4; c++) acc[p][c] = 0ull;

    auto prefetch = [&](int kt) {
        {
            float4 v = make_float4(0.f, 0.f, 0.f, 0.f);
            int gr = row0 + ar0;
            if (gr < NN) v = *(const float4*)(A + (size_t)gr * K + kt + ak4);
            if (PREL) { v.x = lky(v.x); v.y = lky(v.y); v.z = lky(v.z); v.w = lky(v.w); }
            stA0 = v;
        }
        {
            float4 v = make_float4(0.f, 0.f, 0.f, 0.f);
            int gr = row0 + ar0 + 64;
            if (gr < NN) v = *(const float4*)(A + (size_t)gr * K + kt + ak4);
            if (PREL) { v.x = lky(v.x); v.y = lky(v.y); v.z = lky(v.z); v.w = lky(v.w); }
            stA1 = v;
        }
        if (BMODE == 0) {
            int j = col0 + jloc0;
            stB = *(const float4*)(W1 + (size_t)j * K + kt + kloc0);
        } else {
            int kk = kt + kB1;
            float b[4];
#pragma unroll
            for (int i = 0; i < 4; i++) {
                int j = col0 + jB1 + i;
                if (j < HALF) {
                    b[i] = W1[(size_t)kk * HALF + j];
                } else {
                    int jj = j - HALF;
                    b[i] = W2[(size_t)jj * HALF + kk] - W2[(size_t)kk * HALF + jj]
                         - ((kk == jj) ? GAMMA_C : 0.f);
                }
            }
            stB = make_float4(b[0], b[1], b[2], b[3]);
        }
    };
    auto commit = [&](int buf) {
        sA[buf][ak4 + 0][ar0] = stA0.x;
        sA[buf][ak4 + 1][ar0] = stA0.y;
        sA[buf][ak4 + 2][ar0] = stA0.z;
        sA[buf][ak4 + 3][ar0] = stA0.w;
        sA[buf][ak4 + 0][ar0 + 64] = stA1.x;
        sA[buf][ak4 + 1][ar0 + 64] = stA1.y;
        sA[buf][ak4 + 2][ar0 + 64] = stA1.z;
        sA[buf][ak4 + 3][ar0 + 64] = stA1.w;
        if (BMODE == 0) {
            sB[buf][kloc0 + 0][jloc0] = stB.x;
            sB[buf][kloc0 + 1][jloc0] = stB.y;
            sB[buf][kloc0 + 2][jloc0] = stB.z;
            sB[buf][kloc0 + 3][jloc0] = stB.w;
        } else {
            *(float4*)&sB[buf][kB1][jB1] = stB;
        }
    };

    prefetch(0);
    commit(0);
    __syncthreads();

    int cur = 0;
#pragma unroll 1
    for (int t = 0; t < NT; t++) {
        if (t + 1 < NT) prefetch((t + 1) * 16);
#pragma unroll
        for (int k = 0; k < 16; k++) {
            float4 va = *(const float4*)&sA[cur][k][ty * 8];
            float4 vb = *(const float4*)&sA[cur][k][ty * 8 + 4];
            float4 bb = *(const float4*)&sB[cur][k][tx * 4];
            unsigned long long ap0 = pk(va.x, va.y);   // rows 2p=0: (r0,r1)
            unsigned long long ap1 = pk(va.z, va.w);   // (r2,r3)
            unsigned long long ap2 = pk(vb.x, vb.y);   // (r4,r5)
            unsigned long long ap3 = pk(vb.z, vb.w);   // (r6,r7)
            unsigned long long b0 = pk(bb.x, bb.x);
            unsigned long long b1 = pk(bb.y, bb.y);
            unsigned long long b2 = pk(bb.z, bb.z);
            unsigned long long b3 = pk(bb.w, bb.w);
            fma2(acc[0][0], ap0, b0); fma2(acc[0][1], ap0, b1);
            fma2(acc[0][2], ap0, b2); fma2(acc[0][3], ap0, b3);
            fma2(acc[1][0], ap1, b0); fma2(acc[1][1], ap1, b1);
            fma2(acc[1][2], ap1, b2); fma2(acc[1][3], ap1, b3);
            fma2(acc[2][0], ap2, b0); fma2(acc[2][1], ap2, b1);
            fma2(acc[2][2], ap2, b2); fma2(acc[2][3], ap2, b3);
            fma2(acc[3][0], ap3, b0); fma2(acc[3][1], ap3, b1);
            fma2(acc[3][2], ap3, b2); fma2(acc[3][3], ap3, b3);
        }
        if (t + 1 < NT) {
            commit(cur ^ 1);
            __syncthreads();
            cur ^= 1;
        }
    }

    float4 bv = make_float4(0.f, 0.f, 0.f, 0.f);
    if (bias) bv = *(const float4*)(bias + col0 + tx * 4);
#pragma unroll
    for (int p = 0; p < 4; p++) {
        float l0, h0, l1, h1, l2, h2, l3, h3;
        upk(acc[p][0], l0, h0);
        upk(acc[p][1], l1, h1);
        upk(acc[p][2], l2, h2);
        upk(acc[p][3], l3, h3);
        int rl = row0 + ty * 8 + 2 * p;
        if (rl < NN) {
            float4 o = make_float4(l0 + bv.x, l1 + bv.y, l2 + bv.z, l3 + bv.w);
            if (POSTL) { o.x = lky(o.x); o.y = lky(o.y); o.z = lky(o.z); o.w = lky(o.w); }
            *(float4*)(C + (size_t)rl * J + col0 + tx * 4) = o;
        }
        int rh = rl + 1;
        if (rh < NN) {
            float4 o = make_float4(h0 + bv.x, h1 + bv.y, h2 + bv.z, h3 + bv.w);
            if (POSTL) { o.x = lky(o.x); o.y = lky(o.y); o.z = lky(o.z); o.w = lky(o.w); }
            *(float4*)(C + (size_t)rh * J + col0 + tx * 4) = o;
        }
    }
}

// ---------------- fused gather + update, vectorized (verbatim R12) ----------------
template<int H, int RS>
__global__ void __launch_bounds__(256) k_gather_update(float* __restrict__ h,
                                                       const float* __restrict__ buf,
                                                       const float* __restrict__ bias) {
    int node = (blockIdx.x * blockDim.x + threadIdx.x) >> 5;
    if (node >= NN) return;
    int lane = threadIdx.x & 31;
    constexpr int V = H / 32;       // 4 (H=128) or 2 (H=64)
    float di = g_dinv[node];
    const float* mr = buf + (size_t)node * RS + lane * V;
    float acc[V];
#pragma unroll
    for (int c = 0; c < V; c++)
        acc[c] = mr[c] * di * di;   // self loop
    int e0 = g_rowptr[node], e1 = g_rowptr[node + 1];
    int e = e0;
    for (; e + 1 < e1; e += 2) {
        int s0 = g_colidx[e], s1 = g_colidx[e + 1];
        float w0 = g_dinv[s0] * di, w1 = g_dinv[s1] * di;
        const float* m0 = buf + (size_t)s0 * RS + lane * V;
        const float* m1 = buf + (size_t)s1 * RS + lane * V;
        if (V == 4) {
            float4 v0 = *(const float4*)m0;
            float4 v1 = *(const float4*)m1;
            acc[0] = fmaf(v1.x, w1, fmaf(v0.x, w0, acc[0]));
            acc[1] = fmaf(v1.y, w1, fmaf(v0.y, w0, acc[1]));
            acc[2] = fmaf(v1.z, w1, fmaf(v0.z, w0, acc[2]));
            acc[3] = fmaf(v1.w, w1, fmaf(v0.w, w0, acc[3]));
        } else {
            float2 v0 = *(const float2*)m0;
            float2 v1 = *(const float2*)m1;
            acc[0] = fmaf(v1.x, w1, fmaf(v0.x, w0, acc[0]));
            acc[1] = fmaf(v1.y, w1, fmaf(v0.y, w0, acc[1]));
        }
    }
    if (e < e1) {
        int s0 = g_colidx[e];
        float w0 = g_dinv[s0] * di;
        const float* m0 = buf + (size_t)s0 * RS + lane * V;
        if (V == 4) {
            float4 v0 = *(const float4*)m0;
            acc[0] = fmaf(v0.x, w0, acc[0]);
            acc[1] = fmaf(v0.y, w0, acc[1]);
            acc[2] = fmaf(v0.z, w0, acc[2]);
            acc[3] = fmaf(v0.w, w0, acc[3]);
        } else {
            float2 v0 = *(const float2*)m0;
            acc[0] = fmaf(v0.x, w0, acc[0]);
            acc[1] = fmaf(v0.y, w0, acc[1]);
        }
    }
#pragma unroll
    for (int c = 0; c < V; c++) {
        int j = lane * V + c;
        float a = buf[(size_t)node * RS + H + j];   // anti half (includes -gamma*h)
        size_t idx = (size_t)node * H + j;
        h[idx] += EPS_C * tanhf(a + acc[c] + bias[j]);
    }
}

// ---------------- fc + log_softmax, thread per node (verbatim R12) ----------------
__global__ void k_fc(const float* __restrict__ h2, const float* __restrict__ wfc,
                     const float* __restrict__ bfc, float* __restrict__ out) {
    int i = blockIdx.x * blockDim.x + threadIdx.x;
    if (i >= NN) return;
    float hv[64];
    const float* hr = h2 + (size_t)i * 64;
    for (int k = 0; k < 64; k++) hv[k] = hr[k];
    float lg[40];
    float m = -1e30f;
    for (int j = 0; j < 40; j++) {
        float acc = bfc[j];
        for (int k = 0; k < 64; k++)
            acc += hv[k] * wfc[(size_t)j * 64 + k];
        lg[j] = acc;
        m = fmaxf(m, acc);
    }
    float s = 0.f;
    for (int j = 0; j < 40; j++) s += expf(lg[j] - m);
    float lse = m + logf(s);
    float* o = out + (size_t)i * 40;
    for (int j = 0; j < 40; j++) o[j] = lg[j] - lse;
}

// ---------------- launch (layer0 GEMM at capture slot #4) ----------------
extern "C" void kernel_launch(void* const* d_in, const int* in_sizes, int n_in,
                              void* d_out, int out_size) {
    const float* x      = (const float*)d_in[0];
    const void*  edges  = d_in[1];
    const float* w_hid  = (const float*)d_in[2];
    const float* b_hid  = (const float*)d_in[3];
    const float* W_a1   = (const float*)d_in[4];
    const float* gcn_w1 = (const float*)d_in[5];
    const float* b_a1   = (const float*)d_in[6];
    const float* w_hid2 = (const float*)d_in[7];
    const float* b_hid2 = (const float*)d_in[8];
    const float* W_a2   = (const float*)d_in[9];
    const float* gcn_w2 = (const float*)d_in[10];
    const float* b_a2   = (const float*)d_in[11];
    const float* w_fc   = (const float*)d_in[12];
    const float* b_fc   = (const float*)d_in[13];
    float* out = (float*)d_out;

    int gx = (NN + 127) / 128;                 // 391
    int nodeWarps = (NN * 32 + 255) / 256;
    int cvtBlocks = ((EE > NN ? EE : NN) + 255) / 256;

    // #1..#3
    probe_kernel<<<1, 1024>>>((const unsigned int*)edges);
    convert_zero<<<cvtBlocks, 256>>>(edges);
    hist_kernel<<<(EE + 255) / 256, 256>>>();

    // #4: layer0 GEMM  [N,256]->[N,128]   (ncu capture target)
    gemm_kernel<256, 128, 0, 0, 1><<<dim3(gx, 2), 256>>>(x, w_hid, nullptr, b_hid, g_h);

    // rest of preprocessing
    dinv_kernel<<<(NN + 255) / 256, 256>>>();
    scan_kernel<<<1, 1024>>>();
    fill_kernel<<<(EE + 255) / 256, 256>>>();

    // conv1: 3 iterations, H=128
    for (int it = 0; it < 3; it++) {
        gemm_kernel<128, 256, 1, 0, 0><<<dim3(gx, 4), 256>>>(g_h, gcn_w1, W_a1, nullptr, g_buf);
        k_gather_update<128, 256><<<nodeWarps, 256>>>(g_h, g_buf, b_a1);
    }

    // hid2  [N,128]->[N,64]
    gemm_kernel<128, 64, 0, 1, 1><<<dim3(gx, 1), 256>>>(g_h, w_hid2, nullptr, b_hid2, g_h2);

    // conv2: 1 iteration, H=64
    gemm_kernel<64, 128, 1, 0, 0><<<dim3(gx, 2), 256>>>(g_h2, gcn_w2, W_a2, nullptr, g_buf);
    k_gather_update<64, 128><<<nodeWarps, 256>>>(g_h2, g_buf, b_a2);

    // fc + log_softmax
    k_fc<<<(NN + 255) / 256, 256>>>(g_h2, w_fc, b_fc, out);
}